// round 1
// baseline (speedup 1.0000x reference)
#include <cuda_runtime.h>
#include <cuda_bf16.h>
#include <math.h>

#define EMBED   384
#define HEADS   6
#define HEAD_DIM 64
#define MLP_HID 1536
#define NTOK    16384      // B*N = 16*1024
#define SEQ     1024
#define BATCH   16

// ---------------- scratch (device globals; no allocation allowed) ----------
__device__ float g_h  [NTOK * EMBED];     // layernorm output (reused for ln1 & ln2)
__device__ float g_qkv[NTOK * 3 * EMBED]; // qkv projection
__device__ float g_ctx[NTOK * EMBED];     // attention context
__device__ float g_x1 [NTOK * EMBED];     // x after attention residual
__device__ float g_h2 [NTOK * MLP_HID];   // mlp hidden

// ---------------- layernorm: one block per row of 384 ----------------------
__global__ void ln_kernel(const float* __restrict__ x,
                          const float* __restrict__ g,
                          const float* __restrict__ b,
                          float* __restrict__ out)
{
    int row = blockIdx.x;
    int tid = threadIdx.x;             // 128 threads
    const float* xr = x + (size_t)row * EMBED;

    float v[3];
    float s = 0.f, sq = 0.f;
#pragma unroll
    for (int i = 0; i < 3; i++) {
        v[i] = xr[tid + i * 128];
        s  += v[i];
        sq += v[i] * v[i];
    }
#pragma unroll
    for (int o = 16; o > 0; o >>= 1) {
        s  += __shfl_xor_sync(0xffffffffu, s,  o);
        sq += __shfl_xor_sync(0xffffffffu, sq, o);
    }
    __shared__ float ssum[4], ssq[4];
    int wid = tid >> 5, lane = tid & 31;
    if (lane == 0) { ssum[wid] = s; ssq[wid] = sq; }
    __syncthreads();
    s  = ssum[0] + ssum[1] + ssum[2] + ssum[3];
    sq = ssq[0]  + ssq[1]  + ssq[2]  + ssq[3];

    float mean = s * (1.f / EMBED);
    float var  = sq * (1.f / EMBED) - mean * mean;
    float inv  = rsqrtf(var + 1e-5f);

    float* outr = out + (size_t)row * EMBED;
#pragma unroll
    for (int i = 0; i < 3; i++) {
        int c = tid + i * 128;
        outr[c] = (v[i] - mean) * inv * g[c] + b[c];
    }
}

// ---------------- tiled SGEMM:  C[M,N] = A[M,K] @ B[K,N] + bias (+res/gelu)
// EPI: 0 = bias, 1 = bias + residual, 2 = bias + exact GELU
template <int EPI>
__global__ void sgemm_kernel(const float* __restrict__ A,
                             const float* __restrict__ Bm,
                             const float* __restrict__ bias,
                             const float* __restrict__ res,
                             float* __restrict__ C,
                             int M, int N, int K)
{
    __shared__ float As[32][68];   // A tile transposed: As[k][m]
    __shared__ float Bs[32][68];   // B tile:            Bs[k][n]

    int tid = threadIdx.x;          // 256 threads
    int tx = tid & 15, ty = tid >> 4;
    int m0 = blockIdx.y * 64;
    int n0 = blockIdx.x * 64;

    float acc[4][4] = {};

    for (int k0 = 0; k0 < K; k0 += 32) {
        // load A 64x32 -> transposed
#pragma unroll
        for (int i = 0; i < 2; i++) {
            int e  = tid + i * 256;       // 0..511
            int m  = e >> 3;              // 0..63
            int k4 = e & 7;               // 0..7
            float4 va = *(const float4*)(A + (size_t)(m0 + m) * K + k0 + k4 * 4);
            As[k4 * 4 + 0][m] = va.x;
            As[k4 * 4 + 1][m] = va.y;
            As[k4 * 4 + 2][m] = va.z;
            As[k4 * 4 + 3][m] = va.w;
        }
        // load B 32x64
#pragma unroll
        for (int i = 0; i < 2; i++) {
            int e  = tid + i * 256;
            int k  = e >> 4;              // 0..31
            int n4 = e & 15;              // 0..15
            float4 vb = *(const float4*)(Bm + (size_t)(k0 + k) * N + n0 + n4 * 4);
            *(float4*)&Bs[k][n4 * 4] = vb;
        }
        __syncthreads();

#pragma unroll
        for (int kk = 0; kk < 32; kk++) {
            float4 a4 = *(const float4*)&As[kk][ty * 4];
            float4 b4 = *(const float4*)&Bs[kk][tx * 4];
            float av[4] = {a4.x, a4.y, a4.z, a4.w};
            float bv[4] = {b4.x, b4.y, b4.z, b4.w};
#pragma unroll
            for (int ii = 0; ii < 4; ii++)
#pragma unroll
                for (int jj = 0; jj < 4; jj++)
                    acc[ii][jj] += av[ii] * bv[jj];
        }
        __syncthreads();
    }

#pragma unroll
    for (int ii = 0; ii < 4; ii++) {
        int row = m0 + ty * 4 + ii;
#pragma unroll
        for (int jj = 0; jj < 4; jj++) {
            int col = n0 + tx * 4 + jj;
            float v = acc[ii][jj] + bias[col];
            if (EPI == 1) v += res[(size_t)row * N + col];
            if (EPI == 2) v = 0.5f * v * (1.f + erff(v * 0.70710678118654752f));
            C[(size_t)row * N + col] = v;
        }
    }
}

// ---------------- fused attention (flash style) ------------------------------
// grid: (16 q-tiles, 96 bh-pairs), 256 threads.
__global__ void attn_kernel(const float* __restrict__ qkv,
                            float* __restrict__ ctx)
{
    __shared__ float Qs[64][64];
    __shared__ float KP[64][64];   // K^T (swizzled) then reused as P
    __shared__ float Vs[64][64];

    int tid = threadIdx.x;
    int tx = tid & 15, ty = tid >> 4;
    int qt = blockIdx.x;
    int bh = blockIdx.y;
    int b = bh / HEADS, h = bh % HEADS;

    const float* base = qkv + (size_t)b * SEQ * (3 * EMBED) + h * HEAD_DIM;
    int qn0 = qt * 64;

    // load Q tile [64 rows][64 dims]
#pragma unroll
    for (int i = 0; i < 4; i++) {
        int e  = tid + i * 256;
        int r  = e >> 4;
        int d4 = e & 15;
        float4 v = *(const float4*)(base + (size_t)(qn0 + r) * (3 * EMBED) + d4 * 4);
        *(float4*)&Qs[r][d4 * 4] = v;
    }

    float o[4][4] = {};
    float mrow[4], lrow[4];
#pragma unroll
    for (int ii = 0; ii < 4; ii++) { mrow[ii] = -1e30f; lrow[ii] = 0.f; }
    const float scale = 0.125f;   // 1/sqrt(64)

    for (int kt = 0; kt < 16; kt++) {
        __syncthreads();
        int kn0 = kt * 64;
        // load K (transposed, xor-swizzled) and V
#pragma unroll
        for (int i = 0; i < 4; i++) {
            int e  = tid + i * 256;
            int r  = e >> 4;
            int d4 = e & 15;
            const float* rowp = base + (size_t)(kn0 + r) * (3 * EMBED);
            float4 kv = *(const float4*)(rowp + EMBED + d4 * 4);
            int d = d4 * 4;
            KP[d + 0][r ^ (((d + 0) & 15) << 2)] = kv.x;
            KP[d + 1][r ^ (((d + 1) & 15) << 2)] = kv.y;
            KP[d + 2][r ^ (((d + 2) & 15) << 2)] = kv.z;
            KP[d + 3][r ^ (((d + 3) & 15) << 2)] = kv.w;
            float4 vv = *(const float4*)(rowp + 2 * EMBED + d4 * 4);
            *(float4*)&Vs[r][d4 * 4] = vv;
        }
        __syncthreads();

        // S = Q @ K^T  (64x64 tile, 4x4 per thread)
        float s[4][4] = {};
#pragma unroll
        for (int kk = 0; kk < 64; kk++) {
            float qa[4];
#pragma unroll
            for (int ii = 0; ii < 4; ii++) qa[ii] = Qs[ty * 4 + ii][kk];
            int sc = (tx * 4) ^ ((kk & 15) << 2);
            float4 kb4 = *(const float4*)&KP[kk][sc];
            float kb[4] = {kb4.x, kb4.y, kb4.z, kb4.w};
#pragma unroll
            for (int ii = 0; ii < 4; ii++)
#pragma unroll
                for (int jj = 0; jj < 4; jj++)
                    s[ii][jj] += qa[ii] * kb[jj];
        }

        // online softmax (row stats reduced over the 16 tx lanes of each row group)
#pragma unroll
        for (int ii = 0; ii < 4; ii++) {
#pragma unroll
            for (int jj = 0; jj < 4; jj++) s[ii][jj] *= scale;
            float mloc = fmaxf(fmaxf(s[ii][0], s[ii][1]), fmaxf(s[ii][2], s[ii][3]));
#pragma unroll
            for (int off = 1; off < 16; off <<= 1)
                mloc = fmaxf(mloc, __shfl_xor_sync(0xffffffffu, mloc, off));
            float mnew = fmaxf(mrow[ii], mloc);
            float alpha = expf(mrow[ii] - mnew);
            float ls = 0.f;
#pragma unroll
            for (int jj = 0; jj < 4; jj++) {
                s[ii][jj] = expf(s[ii][jj] - mnew);
                ls += s[ii][jj];
            }
#pragma unroll
            for (int off = 1; off < 16; off <<= 1)
                ls += __shfl_xor_sync(0xffffffffu, ls, off);
            lrow[ii] = lrow[ii] * alpha + ls;
            mrow[ii] = mnew;
#pragma unroll
            for (int jj = 0; jj < 4; jj++) o[ii][jj] *= alpha;
        }

        __syncthreads();   // everyone done reading KP (K^T)
        // write P into KP
#pragma unroll
        for (int ii = 0; ii < 4; ii++)
            *(float4*)&KP[ty * 4 + ii][tx * 4] =
                make_float4(s[ii][0], s[ii][1], s[ii][2], s[ii][3]);
        __syncthreads();

        // O += P @ V
#pragma unroll
        for (int kk = 0; kk < 64; kk++) {
            float p4[4];
#pragma unroll
            for (int ii = 0; ii < 4; ii++) p4[ii] = KP[ty * 4 + ii][kk];
            float4 vb4 = *(const float4*)&Vs[kk][tx * 4];
            float vb[4] = {vb4.x, vb4.y, vb4.z, vb4.w};
#pragma unroll
            for (int ii = 0; ii < 4; ii++)
#pragma unroll
                for (int jj = 0; jj < 4; jj++)
                    o[ii][jj] += p4[ii] * vb[jj];
        }
    }

    // normalize and write ctx (B,N,H,D) flattened to (B,N,C)
#pragma unroll
    for (int ii = 0; ii < 4; ii++) {
        float inv = 1.f / lrow[ii];
        int n = qn0 + ty * 4 + ii;
        float4 ov = make_float4(o[ii][0] * inv, o[ii][1] * inv,
                                o[ii][2] * inv, o[ii][3] * inv);
        *(float4*)(ctx + (size_t)(b * SEQ + n) * EMBED + h * HEAD_DIM + tx * 4) = ov;
    }
}

// ---------------- launcher ---------------------------------------------------
extern "C" void kernel_launch(void* const* d_in, const int* in_sizes, int n_in,
                              void* d_out, int out_size)
{
    (void)in_sizes; (void)n_in; (void)out_size;
    const float* x      = (const float*)d_in[0];
    const float* n1g    = (const float*)d_in[1];
    const float* n1b    = (const float*)d_in[2];
    const float* qkv_w  = (const float*)d_in[3];
    const float* qkv_b  = (const float*)d_in[4];
    const float* proj_w = (const float*)d_in[5];
    const float* proj_b = (const float*)d_in[6];
    const float* n2g    = (const float*)d_in[7];
    const float* n2b    = (const float*)d_in[8];
    const float* fc1_w  = (const float*)d_in[9];
    const float* fc1_b  = (const float*)d_in[10];
    const float* fc2_w  = (const float*)d_in[11];
    const float* fc2_b  = (const float*)d_in[12];
    float* out = (float*)d_out;

    float *h, *qkv, *ctx, *x1, *h2;
    cudaGetSymbolAddress((void**)&h,   g_h);
    cudaGetSymbolAddress((void**)&qkv, g_qkv);
    cudaGetSymbolAddress((void**)&ctx, g_ctx);
    cudaGetSymbolAddress((void**)&x1,  g_x1);
    cudaGetSymbolAddress((void**)&h2,  g_h2);

    // 1. ln1
    ln_kernel<<<NTOK, 128>>>(x, n1g, n1b, h);
    // 2. qkv = h @ qkv_w + qkv_b
    sgemm_kernel<0><<<dim3(3 * EMBED / 64, NTOK / 64), 256>>>(
        h, qkv_w, qkv_b, nullptr, qkv, NTOK, 3 * EMBED, EMBED);
    // 3. attention
    attn_kernel<<<dim3(SEQ / 64, BATCH * HEADS), 256>>>(qkv, ctx);
    // 4. x1 = x + ctx @ proj_w + proj_b
    sgemm_kernel<1><<<dim3(EMBED / 64, NTOK / 64), 256>>>(
        ctx, proj_w, proj_b, x, x1, NTOK, EMBED, EMBED);
    // 5. ln2
    ln_kernel<<<NTOK, 128>>>(x1, n2g, n2b, h);
    // 6. h2 = gelu(h @ fc1_w + fc1_b)
    sgemm_kernel<2><<<dim3(MLP_HID / 64, NTOK / 64), 256>>>(
        h, fc1_w, fc1_b, nullptr, h2, NTOK, MLP_HID, EMBED);
    // 7. out = x1 + h2 @ fc2_w + fc2_b
    sgemm_kernel<1><<<dim3(EMBED / 64, NTOK / 64), 256>>>(
        h2, fc2_w, fc2_b, x1, out, NTOK, EMBED, MLP_HID);
}

// round 2
// speedup vs baseline: 2.6113x; 2.6113x over previous
#include <cuda_runtime.h>
#include <math.h>

#define EMBED   384
#define HEADS   6
#define MLP_HID 1536
#define NTOK    16384
#define SEQ     1024
#define BATCH   16
#define QKV_LD  1152   // 3*EMBED

// ---------------- scratch ----------------------------------------------------
__device__ float g_h  [NTOK * EMBED];
__device__ float g_qkv[NTOK * 3 * EMBED];
__device__ float g_ctx[NTOK * EMBED];
__device__ float g_x1 [NTOK * EMBED];
__device__ float g_h2 [NTOK * MLP_HID];

// ---------------- tf32 helpers ------------------------------------------------
__device__ __forceinline__ unsigned f2t(float x) {
    unsigned r; asm("cvt.rna.tf32.f32 %0,%1;" : "=r"(r) : "f"(x)); return r;
}
__device__ __forceinline__ void mma8(float* d, const unsigned* a, const unsigned* b) {
    asm("mma.sync.aligned.m16n8k8.row.col.f32.tf32.tf32.f32 "
        "{%0,%1,%2,%3},{%4,%5,%6,%7},{%8,%9},{%0,%1,%2,%3};"
        : "+f"(d[0]), "+f"(d[1]), "+f"(d[2]), "+f"(d[3])
        : "r"(a[0]), "r"(a[1]), "r"(a[2]), "r"(a[3]), "r"(b[0]), "r"(b[1]));
}

// ---------------- layernorm ---------------------------------------------------
__global__ void ln_kernel(const float* __restrict__ x,
                          const float* __restrict__ g,
                          const float* __restrict__ b,
                          float* __restrict__ out)
{
    int row = blockIdx.x;
    int tid = threadIdx.x;             // 128 threads
    const float* xr = x + (size_t)row * EMBED;

    float v[3];
    float s = 0.f, sq = 0.f;
#pragma unroll
    for (int i = 0; i < 3; i++) {
        v[i] = xr[tid + i * 128];
        s  += v[i];
        sq += v[i] * v[i];
    }
#pragma unroll
    for (int o = 16; o > 0; o >>= 1) {
        s  += __shfl_xor_sync(0xffffffffu, s,  o);
        sq += __shfl_xor_sync(0xffffffffu, sq, o);
    }
    __shared__ float ssum[4], ssq[4];
    int wid = tid >> 5, lane = tid & 31;
    if (lane == 0) { ssum[wid] = s; ssq[wid] = sq; }
    __syncthreads();
    s  = ssum[0] + ssum[1] + ssum[2] + ssum[3];
    sq = ssq[0]  + ssq[1]  + ssq[2]  + ssq[3];

    float mean = s * (1.f / EMBED);
    float var  = sq * (1.f / EMBED) - mean * mean;
    float inv  = rsqrtf(var + 1e-5f);

    float* outr = out + (size_t)row * EMBED;
#pragma unroll
    for (int i = 0; i < 3; i++) {
        int c = tid + i * 128;
        outr[c] = (v[i] - mean) * inv * g[c] + b[c];
    }
}

// ---------------- tensor-core GEMM: C = A[M,K] @ B[K,N] + bias (+res/gelu) ----
// block tile 128x128, BK=16, 8 warps (4x2), warp tile 32x64, double buffered.
#define SA 20    // A smem row stride (16 + 4 pad)
#define SB 136   // B smem row stride (128 + 8 pad)

template <int EPI>
__global__ void __launch_bounds__(256)
gemm_tc(const float* __restrict__ A, const float* __restrict__ B,
        const float* __restrict__ bias, const float* __restrict__ res,
        float* __restrict__ C, int M, int N, int K)
{
    __shared__ unsigned As[2][128 * SA];
    __shared__ unsigned Bs[2][16 * SB];

    int tid  = threadIdx.x;
    int lane = tid & 31, warp = tid >> 5;
    int wm = (warp & 3) * 32;     // warp m offset within block
    int wn = (warp >> 2) * 64;    // warp n offset
    int gid = lane >> 2, tig = lane & 3;
    long m0 = (long)blockIdx.y * 128;
    int  n0 = blockIdx.x * 128;

    // staging coordinates
    int am[2], ak[2], bk[2], bn[2];
#pragma unroll
    for (int i = 0; i < 2; i++) {
        int e = tid + i * 256;
        am[i] = e & 127;  ak[i] = e >> 7;      // A: (m, k4)
        bk[i] = e >> 5;   bn[i] = (e & 31) * 4; // B: (k, n)
    }

    float acc[2][8][4];
#pragma unroll
    for (int a = 0; a < 2; a++)
#pragma unroll
        for (int b2 = 0; b2 < 8; b2++)
#pragma unroll
            for (int c = 0; c < 4; c++) acc[a][b2][c] = 0.f;

    int KT = K / 16;

    // prologue: stage tile 0 into buffer 0
#pragma unroll
    for (int i = 0; i < 2; i++) {
        float4 va = *(const float4*)(A + (m0 + am[i]) * K + ak[i] * 4);
        uint4 ua = make_uint4(f2t(va.x), f2t(va.y), f2t(va.z), f2t(va.w));
        *(uint4*)&As[0][am[i] * SA + ak[i] * 4] = ua;
        float4 vb = *(const float4*)(B + (long)bk[i] * N + n0 + bn[i]);
        uint4 ub = make_uint4(f2t(vb.x), f2t(vb.y), f2t(vb.z), f2t(vb.w));
        *(uint4*)&Bs[0][bk[i] * SB + bn[i]] = ub;
    }

    for (int kt = 0; kt < KT; kt++) {
        int cur = kt & 1;
        // prefetch next tile into registers
        float4 pa[2], pb[2];
        if (kt + 1 < KT) {
            int k0 = (kt + 1) * 16;
#pragma unroll
            for (int i = 0; i < 2; i++) {
                pa[i] = *(const float4*)(A + (m0 + am[i]) * K + k0 + ak[i] * 4);
                pb[i] = *(const float4*)(B + (long)(k0 + bk[i]) * N + n0 + bn[i]);
            }
        }
        __syncthreads();   // current buffer fully staged

        const unsigned* as = As[cur];
        const unsigned* bs = Bs[cur];
#pragma unroll
        for (int ks = 0; ks < 2; ks++) {
            unsigned af[2][4];
#pragma unroll
            for (int mt = 0; mt < 2; mt++) {
                int r = wm + mt * 16 + gid, c = ks * 8 + tig;
                af[mt][0] = as[r * SA + c];
                af[mt][1] = as[(r + 8) * SA + c];
                af[mt][2] = as[r * SA + c + 4];
                af[mt][3] = as[(r + 8) * SA + c + 4];
            }
#pragma unroll
            for (int nt = 0; nt < 8; nt++) {
                unsigned bf[2];
                int c = wn + nt * 8 + gid;
                bf[0] = bs[(ks * 8 + tig) * SB + c];
                bf[1] = bs[(ks * 8 + tig + 4) * SB + c];
                mma8(acc[0][nt], af[0], bf);
                mma8(acc[1][nt], af[1], bf);
            }
        }
        if (kt + 1 < KT) {
            int nxt = cur ^ 1;
#pragma unroll
            for (int i = 0; i < 2; i++) {
                uint4 ua = make_uint4(f2t(pa[i].x), f2t(pa[i].y), f2t(pa[i].z), f2t(pa[i].w));
                *(uint4*)&As[nxt][am[i] * SA + ak[i] * 4] = ua;
                uint4 ub = make_uint4(f2t(pb[i].x), f2t(pb[i].y), f2t(pb[i].z), f2t(pb[i].w));
                *(uint4*)&Bs[nxt][bk[i] * SB + bn[i]] = ub;
            }
        }
    }

    // epilogue
#pragma unroll
    for (int mt = 0; mt < 2; mt++) {
        long r0 = m0 + wm + mt * 16 + gid;
#pragma unroll
        for (int nt = 0; nt < 8; nt++) {
            int cc = n0 + wn + nt * 8 + 2 * tig;
            float b0 = bias[cc], b1 = bias[cc + 1];
#pragma unroll
            for (int half = 0; half < 2; half++) {
                long r = r0 + half * 8;
                float v0 = acc[mt][nt][half * 2 + 0] + b0;
                float v1 = acc[mt][nt][half * 2 + 1] + b1;
                if (EPI == 1) {
                    v0 += res[r * N + cc];
                    v1 += res[r * N + cc + 1];
                }
                if (EPI == 2) {
                    v0 = 0.5f * v0 * (1.f + erff(v0 * 0.70710678118654752f));
                    v1 = 0.5f * v1 * (1.f + erff(v1 * 0.70710678118654752f));
                }
                *(float2*)(C + r * N + cc) = make_float2(v0, v1);
            }
        }
    }
}

// ---------------- tensor-core flash attention ---------------------------------
// grid (16 q-tiles, 96 bh), 128 threads (4 warps). Warp w owns q rows w*16..+15.
#define SK 68    // K/Q/P smem stride (64 + 4)
#define SV 72    // V smem stride (64 + 8)

__global__ void __launch_bounds__(128)
attn_tc(const float* __restrict__ qkv, float* __restrict__ ctx)
{
    __shared__ unsigned Ks[64 * SK];   // Q staging -> K tile -> P tile
    __shared__ unsigned Vs[64 * SV];

    int tid  = threadIdx.x;
    int lane = tid & 31, warp = tid >> 5;
    int gid = lane >> 2, tig = lane & 3;
    int qt = blockIdx.x, bh = blockIdx.y;
    int b = bh / HEADS, h = bh % HEADS;
    const float* base = qkv + (long)b * SEQ * QKV_LD + h * 64;
    int qn0 = qt * 64;

    // stage Q (pre-scaled by 1/8, exact in tf32)
#pragma unroll
    for (int i = 0; i < 8; i++) {
        int e = tid + i * 128;
        int m = e >> 4, d4 = (e & 15) * 4;
        float4 v = *(const float4*)(base + (long)(qn0 + m) * QKV_LD + d4);
        uint4 u = make_uint4(f2t(v.x * 0.125f), f2t(v.y * 0.125f),
                             f2t(v.z * 0.125f), f2t(v.w * 0.125f));
        *(uint4*)&Ks[m * SK + d4] = u;
    }
    __syncthreads();

    // extract Q fragments into registers
    unsigned qf[8][4];
    int qr = warp * 16 + gid;
#pragma unroll
    for (int ks = 0; ks < 8; ks++) {
        int c = ks * 8 + tig;
        qf[ks][0] = Ks[qr * SK + c];
        qf[ks][1] = Ks[(qr + 8) * SK + c];
        qf[ks][2] = Ks[qr * SK + c + 4];
        qf[ks][3] = Ks[(qr + 8) * SK + c + 4];
    }

    float o[8][4];
#pragma unroll
    for (int nt = 0; nt < 8; nt++)
#pragma unroll
        for (int j = 0; j < 4; j++) o[nt][j] = 0.f;
    float mA = -1e30f, mB = -1e30f, lA = 0.f, lB = 0.f;

    for (int kt = 0; kt < 16; kt++) {
        __syncthreads();   // previous iteration done reading Ks/Vs
        int kn0 = kt * 64;
        // stage K and V tiles
#pragma unroll
        for (int i = 0; i < 8; i++) {
            int e = tid + i * 128;
            int m = e >> 4, d4 = (e & 15) * 4;
            const float* rp = base + (long)(kn0 + m) * QKV_LD;
            float4 kv = *(const float4*)(rp + EMBED + d4);
            *(uint4*)&Ks[m * SK + d4] =
                make_uint4(f2t(kv.x), f2t(kv.y), f2t(kv.z), f2t(kv.w));
            float4 vv = *(const float4*)(rp + 2 * EMBED + d4);
            *(uint4*)&Vs[m * SV + d4] =
                make_uint4(f2t(vv.x), f2t(vv.y), f2t(vv.z), f2t(vv.w));
        }
        __syncthreads();

        // S = (Q*scale) @ K^T   (16 x 64 per warp)
        float s[8][4];
#pragma unroll
        for (int nt = 0; nt < 8; nt++)
#pragma unroll
            for (int j = 0; j < 4; j++) s[nt][j] = 0.f;
#pragma unroll
        for (int ks = 0; ks < 8; ks++) {
#pragma unroll
            for (int nt = 0; nt < 8; nt++) {
                unsigned bf[2];
                int n = nt * 8 + gid, c = ks * 8 + tig;
                bf[0] = Ks[n * SK + c];
                bf[1] = Ks[n * SK + c + 4];
                mma8(s[nt], qf[ks], bf);
            }
        }

        // online softmax: rows (qr) -> s[.][0..1], (qr+8) -> s[.][2..3]
        float mlA = -1e30f, mlB = -1e30f;
#pragma unroll
        for (int nt = 0; nt < 8; nt++) {
            mlA = fmaxf(mlA, fmaxf(s[nt][0], s[nt][1]));
            mlB = fmaxf(mlB, fmaxf(s[nt][2], s[nt][3]));
        }
#pragma unroll
        for (int off = 1; off < 4; off <<= 1) {
            mlA = fmaxf(mlA, __shfl_xor_sync(0xffffffffu, mlA, off));
            mlB = fmaxf(mlB, __shfl_xor_sync(0xffffffffu, mlB, off));
        }
        float mnA = fmaxf(mA, mlA), mnB = fmaxf(mB, mlB);
        float aA = __expf(mA - mnA), aB = __expf(mB - mnB);
        float lsA = 0.f, lsB = 0.f;
#pragma unroll
        for (int nt = 0; nt < 8; nt++) {
            s[nt][0] = __expf(s[nt][0] - mnA); lsA += s[nt][0];
            s[nt][1] = __expf(s[nt][1] - mnA); lsA += s[nt][1];
            s[nt][2] = __expf(s[nt][2] - mnB); lsB += s[nt][2];
            s[nt][3] = __expf(s[nt][3] - mnB); lsB += s[nt][3];
        }
#pragma unroll
        for (int off = 1; off < 4; off <<= 1) {
            lsA += __shfl_xor_sync(0xffffffffu, lsA, off);
            lsB += __shfl_xor_sync(0xffffffffu, lsB, off);
        }
        lA = lA * aA + lsA; mA = mnA;
        lB = lB * aB + lsB; mB = mnB;
#pragma unroll
        for (int nt = 0; nt < 8; nt++) {
            o[nt][0] *= aA; o[nt][1] *= aA;
            o[nt][2] *= aB; o[nt][3] *= aB;
        }

        __syncthreads();   // all warps done reading Ks (K^T)
        // write P into Ks as [q row][key]
#pragma unroll
        for (int nt = 0; nt < 8; nt++) {
            int col = nt * 8 + 2 * tig;
            *(uint2*)&Ks[qr * SK + col] =
                make_uint2(f2t(s[nt][0]), f2t(s[nt][1]));
            *(uint2*)&Ks[(qr + 8) * SK + col] =
                make_uint2(f2t(s[nt][2]), f2t(s[nt][3]));
        }
        __syncthreads();

        // O += P @ V
#pragma unroll
        for (int ks = 0; ks < 8; ks++) {
            unsigned pf[4];
            int c = ks * 8 + tig;
            pf[0] = Ks[qr * SK + c];
            pf[1] = Ks[(qr + 8) * SK + c];
            pf[2] = Ks[qr * SK + c + 4];
            pf[3] = Ks[(qr + 8) * SK + c + 4];
#pragma unroll
            for (int nt = 0; nt < 8; nt++) {
                unsigned bf[2];
                int n = nt * 8 + gid;
                bf[0] = Vs[(ks * 8 + tig) * SV + n];
                bf[1] = Vs[(ks * 8 + tig + 4) * SV + n];
                mma8(o[nt], pf, bf);
            }
        }
    }

    // normalize + write ctx (B,N,C)
    float rA = 1.f / lA, rB = 1.f / lB;
    long row0 = (long)(b * SEQ + qn0 + qr);
#pragma unroll
    for (int nt = 0; nt < 8; nt++) {
        int col = h * 64 + nt * 8 + 2 * tig;
        *(float2*)(ctx + row0 * EMBED + col) =
            make_float2(o[nt][0] * rA, o[nt][1] * rA);
        *(float2*)(ctx + (row0 + 8) * EMBED + col) =
            make_float2(o[nt][2] * rB, o[nt][3] * rB);
    }
}

// ---------------- launcher ----------------------------------------------------
extern "C" void kernel_launch(void* const* d_in, const int* in_sizes, int n_in,
                              void* d_out, int out_size)
{
    (void)in_sizes; (void)n_in; (void)out_size;
    const float* x      = (const float*)d_in[0];
    const float* n1g    = (const float*)d_in[1];
    const float* n1b    = (const float*)d_in[2];
    const float* qkv_w  = (const float*)d_in[3];
    const float* qkv_b  = (const float*)d_in[4];
    const float* proj_w = (const float*)d_in[5];
    const float* proj_b = (const float*)d_in[6];
    const float* n2g    = (const float*)d_in[7];
    const float* n2b    = (const float*)d_in[8];
    const float* fc1_w  = (const float*)d_in[9];
    const float* fc1_b  = (const float*)d_in[10];
    const float* fc2_w  = (const float*)d_in[11];
    const float* fc2_b  = (const float*)d_in[12];
    float* out = (float*)d_out;

    float *h, *qkv, *ctx, *x1, *h2;
    cudaGetSymbolAddress((void**)&h,   g_h);
    cudaGetSymbolAddress((void**)&qkv, g_qkv);
    cudaGetSymbolAddress((void**)&ctx, g_ctx);
    cudaGetSymbolAddress((void**)&x1,  g_x1);
    cudaGetSymbolAddress((void**)&h2,  g_h2);

    ln_kernel<<<NTOK, 128>>>(x, n1g, n1b, h);
    gemm_tc<0><<<dim3(3 * EMBED / 128, NTOK / 128), 256>>>(
        h, qkv_w, qkv_b, nullptr, qkv, NTOK, 3 * EMBED, EMBED);
    attn_tc<<<dim3(SEQ / 64, BATCH * HEADS), 128>>>(qkv, ctx);
    gemm_tc<1><<<dim3(EMBED / 128, NTOK / 128), 256>>>(
        ctx, proj_w, proj_b, x, x1, NTOK, EMBED, EMBED);
    ln_kernel<<<NTOK, 128>>>(x1, n2g, n2b, h);
    gemm_tc<2><<<dim3(MLP_HID / 128, NTOK / 128), 256>>>(
        h, fc1_w, fc1_b, nullptr, h2, NTOK, MLP_HID, EMBED);
    gemm_tc<1><<<dim3(EMBED / 128, NTOK / 128), 256>>>(
        h2, fc2_w, fc2_b, x1, out, NTOK, EMBED, MLP_HID);
}

// round 3
// speedup vs baseline: 3.0246x; 1.1582x over previous
#include <cuda_runtime.h>
#include <math.h>

#define EMBED   384
#define HEADS   6
#define MLP_HID 1536
#define NTOK    16384
#define SEQ     1024
#define BATCH   16
#define QKV_LD  1152   // 3*EMBED

// ---------------- scratch ----------------------------------------------------
__device__ float g_h  [NTOK * EMBED];
__device__ float g_qkv[NTOK * 3 * EMBED];
__device__ float g_ctx[NTOK * EMBED];
__device__ float g_x1 [NTOK * EMBED];
__device__ float g_h2 [NTOK * MLP_HID];

// ---------------- helpers -----------------------------------------------------
__device__ __forceinline__ unsigned f2t(float x) {
    unsigned r; asm("cvt.rna.tf32.f32 %0,%1;" : "=r"(r) : "f"(x)); return r;
}
__device__ __forceinline__ void mma8(float* d, const unsigned* a, const unsigned* b) {
    asm("mma.sync.aligned.m16n8k8.row.col.f32.tf32.tf32.f32 "
        "{%0,%1,%2,%3},{%4,%5,%6,%7},{%8,%9},{%0,%1,%2,%3};"
        : "+f"(d[0]), "+f"(d[1]), "+f"(d[2]), "+f"(d[3])
        : "r"(a[0]), "r"(a[1]), "r"(a[2]), "r"(a[3]), "r"(b[0]), "r"(b[1]));
}
__device__ __forceinline__ void cpa16(unsigned dst, const void* src) {
    asm volatile("cp.async.ca.shared.global [%0], [%1], 16;" :: "r"(dst), "l"(src));
}
__device__ __forceinline__ unsigned sptr(const void* p) {
    return (unsigned)__cvta_generic_to_shared(p);
}
#define CP_COMMIT() asm volatile("cp.async.commit_group;")
#define CP_WAIT(n)  asm volatile("cp.async.wait_group %0;" :: "n"(n))

// ---------------- layernorm ---------------------------------------------------
__global__ void ln_kernel(const float* __restrict__ x,
                          const float* __restrict__ g,
                          const float* __restrict__ b,
                          float* __restrict__ out)
{
    int row = blockIdx.x;
    int tid = threadIdx.x;             // 128 threads
    const float* xr = x + (size_t)row * EMBED;

    float v[3];
    float s = 0.f, sq = 0.f;
#pragma unroll
    for (int i = 0; i < 3; i++) {
        v[i] = xr[tid + i * 128];
        s  += v[i];
        sq += v[i] * v[i];
    }
#pragma unroll
    for (int o = 16; o > 0; o >>= 1) {
        s  += __shfl_xor_sync(0xffffffffu, s,  o);
        sq += __shfl_xor_sync(0xffffffffu, sq, o);
    }
    __shared__ float ssum[4], ssq[4];
    int wid = tid >> 5, lane = tid & 31;
    if (lane == 0) { ssum[wid] = s; ssq[wid] = sq; }
    __syncthreads();
    s  = ssum[0] + ssum[1] + ssum[2] + ssum[3];
    sq = ssq[0]  + ssq[1]  + ssq[2]  + ssq[3];

    float mean = s * (1.f / EMBED);
    float var  = sq * (1.f / EMBED) - mean * mean;
    float inv  = rsqrtf(var + 1e-5f);

    float* outr = out + (size_t)row * EMBED;
#pragma unroll
    for (int i = 0; i < 3; i++) {
        int c = tid + i * 128;
        outr[c] = (v[i] - mean) * inv * g[c] + b[c];
    }
}

// ---------------- tensor-core GEMM (cp.async 3-stage) -------------------------
// block 128x128, BK=16, 8 warps (4x2), warp tile 32x64.
#define SA 20    // A smem row stride floats (16+4), 80B rows (16B aligned)
#define SB 136   // B smem row stride floats (128+8), 544B rows (16B aligned)
#define GSM_A (128 * SA)
#define GSM_B (16 * SB)
#define GEMM_SMEM ((3 * (GSM_A + GSM_B)) * 4)

template <int EPI>
__global__ void __launch_bounds__(256)
gemm_tc(const float* __restrict__ A, const float* __restrict__ B,
        const float* __restrict__ bias, const float* __restrict__ res,
        float* __restrict__ C, int M, int N, int K)
{
    extern __shared__ float sm[];
    float* As = sm;                 // [3][128*SA]
    float* Bs = sm + 3 * GSM_A;     // [3][16*SB]

    int tid  = threadIdx.x;
    int lane = tid & 31, warp = tid >> 5;
    int wm = (warp & 3) * 32;
    int wn = (warp >> 2) * 64;
    int gid = lane >> 2, tig = lane & 3;
    long m0 = (long)blockIdx.y * 128;
    int  n0 = blockIdx.x * 128;

    // staging chunk coordinates (2 x 16B chunks each for A and B per thread)
    int am[2], aj[2], bk[2], bj[2];
#pragma unroll
    for (int i = 0; i < 2; i++) {
        int e = tid + i * 256;      // 0..511
        am[i] = e >> 2;  aj[i] = e & 3;    // A: (row m, 4-float chunk)
        bk[i] = e >> 5;  bj[i] = e & 31;   // B: (row k, 4-float chunk)
    }

    float acc[2][8][4];
#pragma unroll
    for (int a = 0; a < 2; a++)
#pragma unroll
        for (int b2 = 0; b2 < 8; b2++)
#pragma unroll
            for (int c = 0; c < 4; c++) acc[a][b2][c] = 0.f;

    int KT = K / 16;

    // prologue: stages 0 and 1
#pragma unroll
    for (int s = 0; s < 2; s++) {
        int k0 = s * 16;
#pragma unroll
        for (int i = 0; i < 2; i++) {
            cpa16(sptr(&As[s * GSM_A + am[i] * SA + aj[i] * 4]),
                  A + (m0 + am[i]) * K + k0 + aj[i] * 4);
            cpa16(sptr(&Bs[s * GSM_B + bk[i] * SB + bj[i] * 4]),
                  B + (long)(k0 + bk[i]) * N + n0 + bj[i] * 4);
        }
        CP_COMMIT();
    }

    for (int kt = 0; kt < KT; kt++) {
        CP_WAIT(1);
        __syncthreads();

        // issue stage kt+2
        if (kt + 2 < KT) {
            int s = (kt + 2) % 3;
            int k0 = (kt + 2) * 16;
#pragma unroll
            for (int i = 0; i < 2; i++) {
                cpa16(sptr(&As[s * GSM_A + am[i] * SA + aj[i] * 4]),
                      A + (m0 + am[i]) * K + k0 + aj[i] * 4);
                cpa16(sptr(&Bs[s * GSM_B + bk[i] * SB + bj[i] * 4]),
                      B + (long)(k0 + bk[i]) * N + n0 + bj[i] * 4);
            }
        }
        CP_COMMIT();

        const float* as = As + (kt % 3) * GSM_A;
        const float* bs = Bs + (kt % 3) * GSM_B;
#pragma unroll
        for (int ks = 0; ks < 2; ks++) {
            unsigned af[2][4];
#pragma unroll
            for (int mt = 0; mt < 2; mt++) {
                int r = wm + mt * 16 + gid, c = ks * 8 + tig;
                af[mt][0] = f2t(as[r * SA + c]);
                af[mt][1] = f2t(as[(r + 8) * SA + c]);
                af[mt][2] = f2t(as[r * SA + c + 4]);
                af[mt][3] = f2t(as[(r + 8) * SA + c + 4]);
            }
#pragma unroll
            for (int nt = 0; nt < 8; nt++) {
                unsigned bf[2];
                int c2 = wn + nt * 8 + gid;
                bf[0] = f2t(bs[(ks * 8 + tig) * SB + c2]);
                bf[1] = f2t(bs[(ks * 8 + tig + 4) * SB + c2]);
                mma8(acc[0][nt], af[0], bf);
                mma8(acc[1][nt], af[1], bf);
            }
        }
    }

    // epilogue
#pragma unroll
    for (int mt = 0; mt < 2; mt++) {
        long r0 = m0 + wm + mt * 16 + gid;
#pragma unroll
        for (int nt = 0; nt < 8; nt++) {
            int cc = n0 + wn + nt * 8 + 2 * tig;
            float b0 = bias[cc], b1 = bias[cc + 1];
#pragma unroll
            for (int half = 0; half < 2; half++) {
                long r = r0 + half * 8;
                float v0 = acc[mt][nt][half * 2 + 0] + b0;
                float v1 = acc[mt][nt][half * 2 + 1] + b1;
                if (EPI == 1) {
                    v0 += res[r * N + cc];
                    v1 += res[r * N + cc + 1];
                }
                if (EPI == 2) {
                    v0 = 0.5f * v0 * (1.f + erff(v0 * 0.70710678118654752f));
                    v1 = 0.5f * v1 * (1.f + erff(v1 * 0.70710678118654752f));
                }
                *(float2*)(C + r * N + cc) = make_float2(v0, v1);
            }
        }
    }
}

// ---------------- tensor-core flash attention (cp.async, warp-private P) ------
#define SK 68    // 64+4 floats (272B rows, 16B aligned)
#define SV 72    // 64+8 floats (288B rows, 16B aligned)
#define AT_PQ   (64 * SK)                       // Q staging / P buffer (uint)
#define AT_K    (64 * SK)
#define AT_V    (64 * SV)
#define ATT_SMEM ((AT_PQ + 2 * AT_K + 2 * AT_V) * 4)

__global__ void __launch_bounds__(128)
attn_tc(const float* __restrict__ qkv, float* __restrict__ ctx)
{
    extern __shared__ unsigned smu[];
    unsigned* PQ = smu;                       // Q staging -> per-warp P rows
    float* Ks = (float*)(smu + AT_PQ);        // [2][64*SK]
    float* Vs = (float*)(smu + AT_PQ + 2 * AT_K);   // [2][64*SV]

    int tid  = threadIdx.x;
    int lane = tid & 31, warp = tid >> 5;
    int gid = lane >> 2, tig = lane & 3;
    int qt = blockIdx.x, bh = blockIdx.y;
    int b = bh / HEADS, h = bh % HEADS;
    const float* base = qkv + (long)b * SEQ * QKV_LD + h * 64;
    int qn0 = qt * 64;

    // chunk coords: 1024 16B-chunks per 64x64 tile, 8 per thread
    int cm[8], cj[8];
#pragma unroll
    for (int i = 0; i < 8; i++) {
        int e = tid + i * 128;
        cm[i] = e >> 4; cj[i] = (e & 15) * 4;
    }

    // prologue: stage Q (group 0), K/V tile 0 (group 1)
#pragma unroll
    for (int i = 0; i < 8; i++)
        cpa16(sptr(&PQ[cm[i] * SK + cj[i]]),
              base + (long)(qn0 + cm[i]) * QKV_LD + cj[i]);
    CP_COMMIT();
#pragma unroll
    for (int i = 0; i < 8; i++) {
        const float* rp = base + (long)cm[i] * QKV_LD;
        cpa16(sptr(&Ks[cm[i] * SK + cj[i]]), rp + EMBED + cj[i]);
        cpa16(sptr(&Vs[cm[i] * SV + cj[i]]), rp + 2 * EMBED + cj[i]);
    }
    CP_COMMIT();

    CP_WAIT(1);            // Q arrived
    __syncthreads();

    // extract Q fragments (prescaled by 1/8, exact) — own-warp rows only
    unsigned qf[8][4];
    int qr = warp * 16 + gid;
#pragma unroll
    for (int ks = 0; ks < 8; ks++) {
        int c = ks * 8 + tig;
        qf[ks][0] = f2t(__uint_as_float(PQ[qr * SK + c]) * 0.125f);
        qf[ks][1] = f2t(__uint_as_float(PQ[(qr + 8) * SK + c]) * 0.125f);
        qf[ks][2] = f2t(__uint_as_float(PQ[qr * SK + c + 4]) * 0.125f);
        qf[ks][3] = f2t(__uint_as_float(PQ[(qr + 8) * SK + c + 4]) * 0.125f);
    }

    float o[8][4];
#pragma unroll
    for (int nt = 0; nt < 8; nt++)
#pragma unroll
        for (int j = 0; j < 4; j++) o[nt][j] = 0.f;
    float mA = -1e30f, mB = -1e30f, lA = 0.f, lB = 0.f;

    for (int kt = 0; kt < 16; kt++) {
        CP_WAIT(0);              // K/V tile kt resident
        __syncthreads();         // everyone done with buffer (kt+1)&1 from kt-1

        // issue K/V tile kt+1
        if (kt + 1 < 16) {
            int bufn = (kt + 1) & 1;
            int kn0 = (kt + 1) * 64;
#pragma unroll
            for (int i = 0; i < 8; i++) {
                const float* rp = base + (long)(kn0 + cm[i]) * QKV_LD;
                cpa16(sptr(&Ks[bufn * AT_K + cm[i] * SK + cj[i]]), rp + EMBED + cj[i]);
                cpa16(sptr(&Vs[bufn * AT_V + cm[i] * SV + cj[i]]), rp + 2 * EMBED + cj[i]);
            }
        }
        CP_COMMIT();

        const float* kb = Ks + (kt & 1) * AT_K;
        const float* vb = Vs + (kt & 1) * AT_V;

        // S = (Q/8) @ K^T
        float s[8][4];
#pragma unroll
        for (int nt = 0; nt < 8; nt++)
#pragma unroll
            for (int j = 0; j < 4; j++) s[nt][j] = 0.f;
#pragma unroll
        for (int ks = 0; ks < 8; ks++) {
            int c = ks * 8 + tig;
#pragma unroll
            for (int nt = 0; nt < 8; nt++) {
                unsigned bf[2];
                int n = nt * 8 + gid;
                bf[0] = f2t(kb[n * SK + c]);
                bf[1] = f2t(kb[n * SK + c + 4]);
                mma8(s[nt], qf[ks], bf);
            }
        }

        // online softmax
        float mlA = -1e30f, mlB = -1e30f;
#pragma unroll
        for (int nt = 0; nt < 8; nt++) {
            mlA = fmaxf(mlA, fmaxf(s[nt][0], s[nt][1]));
            mlB = fmaxf(mlB, fmaxf(s[nt][2], s[nt][3]));
        }
#pragma unroll
        for (int off = 1; off < 4; off <<= 1) {
            mlA = fmaxf(mlA, __shfl_xor_sync(0xffffffffu, mlA, off));
            mlB = fmaxf(mlB, __shfl_xor_sync(0xffffffffu, mlB, off));
        }
        float mnA = fmaxf(mA, mlA), mnB = fmaxf(mB, mlB);
        float aA = __expf(mA - mnA), aB = __expf(mB - mnB);
        float lsA = 0.f, lsB = 0.f;
#pragma unroll
        for (int nt = 0; nt < 8; nt++) {
            s[nt][0] = __expf(s[nt][0] - mnA); lsA += s[nt][0];
            s[nt][1] = __expf(s[nt][1] - mnA); lsA += s[nt][1];
            s[nt][2] = __expf(s[nt][2] - mnB); lsB += s[nt][2];
            s[nt][3] = __expf(s[nt][3] - mnB); lsB += s[nt][3];
        }
#pragma unroll
        for (int off = 1; off < 4; off <<= 1) {
            lsA += __shfl_xor_sync(0xffffffffu, lsA, off);
            lsB += __shfl_xor_sync(0xffffffffu, lsB, off);
        }
        lA = lA * aA + lsA; mA = mnA;
        lB = lB * aB + lsB; mB = mnB;
#pragma unroll
        for (int nt = 0; nt < 8; nt++) {
            o[nt][0] *= aA; o[nt][1] *= aA;
            o[nt][2] *= aB; o[nt][3] *= aB;
        }

        // P -> warp-private smem rows (no block barrier needed)
#pragma unroll
        for (int nt = 0; nt < 8; nt++) {
            int col = nt * 8 + 2 * tig;
            *(uint2*)&PQ[qr * SK + col] =
                make_uint2(f2t(s[nt][0]), f2t(s[nt][1]));
            *(uint2*)&PQ[(qr + 8) * SK + col] =
                make_uint2(f2t(s[nt][2]), f2t(s[nt][3]));
        }
        __syncwarp();

        // O += P @ V
#pragma unroll
        for (int ks = 0; ks < 8; ks++) {
            unsigned pf[4];
            int c = ks * 8 + tig;
            pf[0] = PQ[qr * SK + c];
            pf[1] = PQ[(qr + 8) * SK + c];
            pf[2] = PQ[qr * SK + c + 4];
            pf[3] = PQ[(qr + 8) * SK + c + 4];
#pragma unroll
            for (int nt = 0; nt < 8; nt++) {
                unsigned bf[2];
                int n = nt * 8 + gid;
                bf[0] = f2t(vb[(ks * 8 + tig) * SV + n]);
                bf[1] = f2t(vb[(ks * 8 + tig + 4) * SV + n]);
                mma8(o[nt], pf, bf);
            }
        }
        __syncwarp();   // pf reads done before next iteration's P overwrite
    }

    // normalize + write ctx (B,N,C)
    float rA = 1.f / lA, rB = 1.f / lB;
    long row0 = (long)(b * SEQ + qn0 + qr);
#pragma unroll
    for (int nt = 0; nt < 8; nt++) {
        int col = h * 64 + nt * 8 + 2 * tig;
        *(float2*)(ctx + row0 * EMBED + col) =
            make_float2(o[nt][0] * rA, o[nt][1] * rA);
        *(float2*)(ctx + (row0 + 8) * EMBED + col) =
            make_float2(o[nt][2] * rB, o[nt][3] * rB);
    }
}

// ---------------- launcher ----------------------------------------------------
extern "C" void kernel_launch(void* const* d_in, const int* in_sizes, int n_in,
                              void* d_out, int out_size)
{
    (void)in_sizes; (void)n_in; (void)out_size;
    const float* x      = (const float*)d_in[0];
    const float* n1g    = (const float*)d_in[1];
    const float* n1b    = (const float*)d_in[2];
    const float* qkv_w  = (const float*)d_in[3];
    const float* qkv_b  = (const float*)d_in[4];
    const float* proj_w = (const float*)d_in[5];
    const float* proj_b = (const float*)d_in[6];
    const float* n2g    = (const float*)d_in[7];
    const float* n2b    = (const float*)d_in[8];
    const float* fc1_w  = (const float*)d_in[9];
    const float* fc1_b  = (const float*)d_in[10];
    const float* fc2_w  = (const float*)d_in[11];
    const float* fc2_b  = (const float*)d_in[12];
    float* out = (float*)d_out;

    float *h, *qkv, *ctx, *x1, *h2;
    cudaGetSymbolAddress((void**)&h,   g_h);
    cudaGetSymbolAddress((void**)&qkv, g_qkv);
    cudaGetSymbolAddress((void**)&ctx, g_ctx);
    cudaGetSymbolAddress((void**)&x1,  g_x1);
    cudaGetSymbolAddress((void**)&h2,  g_h2);

    cudaFuncSetAttribute(gemm_tc<0>, cudaFuncAttributeMaxDynamicSharedMemorySize, GEMM_SMEM);
    cudaFuncSetAttribute(gemm_tc<1>, cudaFuncAttributeMaxDynamicSharedMemorySize, GEMM_SMEM);
    cudaFuncSetAttribute(gemm_tc<2>, cudaFuncAttributeMaxDynamicSharedMemorySize, GEMM_SMEM);
    cudaFuncSetAttribute(attn_tc,    cudaFuncAttributeMaxDynamicSharedMemorySize, ATT_SMEM);

    ln_kernel<<<NTOK, 128>>>(x, n1g, n1b, h);
    gemm_tc<0><<<dim3(3 * EMBED / 128, NTOK / 128), 256, GEMM_SMEM>>>(
        h, qkv_w, qkv_b, nullptr, qkv, NTOK, 3 * EMBED, EMBED);
    attn_tc<<<dim3(SEQ / 64, BATCH * HEADS), 128, ATT_SMEM>>>(qkv, ctx);
    gemm_tc<1><<<dim3(EMBED / 128, NTOK / 128), 256, GEMM_SMEM>>>(
        ctx, proj_w, proj_b, x, x1, NTOK, EMBED, EMBED);
    ln_kernel<<<NTOK, 128>>>(x1, n2g, n2b, h);
    gemm_tc<2><<<dim3(MLP_HID / 128, NTOK / 128), 256, GEMM_SMEM>>>(
        h, fc1_w, fc1_b, nullptr, h2, NTOK, MLP_HID, EMBED);
    gemm_tc<1><<<dim3(EMBED / 128, NTOK / 128), 256, GEMM_SMEM>>>(
        h2, fc2_w, fc2_b, x1, out, NTOK, EMBED, MLP_HID);
}

// round 4
// speedup vs baseline: 3.3309x; 1.1013x over previous
#include <cuda_runtime.h>
#include <math.h>

#define EMBED   384
#define HEADS   6
#define MLP_HID 1536
#define NTOK    16384
#define SEQ     1024
#define BATCH   16
#define QKV_LD  1152   // 3*EMBED

// weight region sizes (floats)
#define WSZ_QKV (EMBED * 3 * EMBED)        // 442368
#define WSZ_PROJ (EMBED * EMBED)           // 147456
#define WSZ_FC1 (EMBED * MLP_HID)          // 589824
#define WSZ_FC2 (MLP_HID * EMBED)          // 589824
#define WSZ_TOT (WSZ_QKV + WSZ_PROJ + WSZ_FC1 + WSZ_FC2)

// ---------------- scratch ----------------------------------------------------
__device__ float g_h  [NTOK * EMBED];
__device__ float g_qkv[NTOK * 3 * EMBED];
__device__ float g_ctx[NTOK * EMBED];
__device__ float g_x1 [NTOK * EMBED];
__device__ float g_h2 [NTOK * MLP_HID];
__device__ float g_w  [WSZ_TOT];           // tf32-rounded weights

// ---------------- helpers -----------------------------------------------------
__device__ __forceinline__ unsigned f2t(float x) {
    unsigned r; asm("cvt.rna.tf32.f32 %0,%1;" : "=r"(r) : "f"(x)); return r;
}
__device__ __forceinline__ float f2tf(float x) { return __uint_as_float(f2t(x)); }
__device__ __forceinline__ void mma8(float* d, const unsigned* a, const unsigned* b) {
    asm("mma.sync.aligned.m16n8k8.row.col.f32.tf32.tf32.f32 "
        "{%0,%1,%2,%3},{%4,%5,%6,%7},{%8,%9},{%0,%1,%2,%3};"
        : "+f"(d[0]), "+f"(d[1]), "+f"(d[2]), "+f"(d[3])
        : "r"(a[0]), "r"(a[1]), "r"(a[2]), "r"(a[3]), "r"(b[0]), "r"(b[1]));
}
__device__ __forceinline__ void cpa16(unsigned dst, const void* src) {
    asm volatile("cp.async.ca.shared.global [%0], [%1], 16;" :: "r"(dst), "l"(src));
}
__device__ __forceinline__ unsigned sptr(const void* p) {
    return (unsigned)__cvta_generic_to_shared(p);
}
#define CP_COMMIT() asm volatile("cp.async.commit_group;")
#define CP_WAIT(n)  asm volatile("cp.async.wait_group %0;" :: "n"(n))

// ---------------- weight pre-rounding (once per call, ~3us) --------------------
__global__ void cvt_weights(const float* __restrict__ w0, const float* __restrict__ w1,
                            const float* __restrict__ w2, const float* __restrict__ w3,
                            float* __restrict__ dst)
{
    int i = blockIdx.x * blockDim.x + threadIdx.x;   // chunk of 4 floats
    int e = i * 4;
    const float* src; int off;
    if      (e < WSZ_QKV)                       { src = w0; off = e; }
    else if (e < WSZ_QKV + WSZ_PROJ)            { src = w1; off = e - WSZ_QKV; }
    else if (e < WSZ_QKV + WSZ_PROJ + WSZ_FC1)  { src = w2; off = e - WSZ_QKV - WSZ_PROJ; }
    else                                        { src = w3; off = e - WSZ_QKV - WSZ_PROJ - WSZ_FC1; }
    float4 v = *(const float4*)(src + off);
    *(uint4*)(dst + e) = make_uint4(f2t(v.x), f2t(v.y), f2t(v.z), f2t(v.w));
}

// ---------------- layernorm (writes tf32-rounded output) ----------------------
__global__ void ln_kernel(const float* __restrict__ x,
                          const float* __restrict__ g,
                          const float* __restrict__ b,
                          float* __restrict__ out)
{
    int row = blockIdx.x;
    int tid = threadIdx.x;             // 128 threads
    const float* xr = x + (size_t)row * EMBED;

    float v[3];
    float s = 0.f, sq = 0.f;
#pragma unroll
    for (int i = 0; i < 3; i++) {
        v[i] = xr[tid + i * 128];
        s  += v[i];
        sq += v[i] * v[i];
    }
#pragma unroll
    for (int o = 16; o > 0; o >>= 1) {
        s  += __shfl_xor_sync(0xffffffffu, s,  o);
        sq += __shfl_xor_sync(0xffffffffu, sq, o);
    }
    __shared__ float ssum[4], ssq[4];
    int wid = tid >> 5, lane = tid & 31;
    if (lane == 0) { ssum[wid] = s; ssq[wid] = sq; }
    __syncthreads();
    s  = ssum[0] + ssum[1] + ssum[2] + ssum[3];
    sq = ssq[0]  + ssq[1]  + ssq[2]  + ssq[3];

    float mean = s * (1.f / EMBED);
    float var  = sq * (1.f / EMBED) - mean * mean;
    float inv  = rsqrtf(var + 1e-5f);

    float* outr = out + (size_t)row * EMBED;
#pragma unroll
    for (int i = 0; i < 3; i++) {
        int c = tid + i * 128;
        outr[c] = f2tf((v[i] - mean) * inv * g[c] + b[c]);
    }
}

// ---------------- tensor-core GEMM (cp.async 3-stage, cvt-free mainloop) ------
// block 128x128, BK=16, 8 warps (4x2), warp tile 32x64.
// EPI: 0 = bias, round to tf32 (feeds attention)
//      1 = bias + residual, full fp32 (residual stream / final out)
//      2 = bias + GELU, round to tf32 (feeds fc2)
#define SA 20
#define SB 136
#define GSM_A (128 * SA)
#define GSM_B (16 * SB)
#define GEMM_SMEM ((3 * (GSM_A + GSM_B)) * 4)

template <int EPI>
__global__ void __launch_bounds__(256)
gemm_tc(const float* __restrict__ A, const float* __restrict__ B,
        const float* __restrict__ bias, const float* __restrict__ res,
        float* __restrict__ C, int M, int N, int K)
{
    extern __shared__ float sm[];
    float* As = sm;                 // [3][128*SA]
    float* Bs = sm + 3 * GSM_A;     // [3][16*SB]

    int tid  = threadIdx.x;
    int lane = tid & 31, warp = tid >> 5;
    int wm = (warp & 3) * 32;
    int wn = (warp >> 2) * 64;
    int gid = lane >> 2, tig = lane & 3;
    long m0 = (long)blockIdx.y * 128;
    int  n0 = blockIdx.x * 128;

    int am[2], aj[2], bk[2], bj[2];
#pragma unroll
    for (int i = 0; i < 2; i++) {
        int e = tid + i * 256;
        am[i] = e >> 2;  aj[i] = e & 3;
        bk[i] = e >> 5;  bj[i] = e & 31;
    }

    float acc[2][8][4];
#pragma unroll
    for (int a = 0; a < 2; a++)
#pragma unroll
        for (int b2 = 0; b2 < 8; b2++)
#pragma unroll
            for (int c = 0; c < 4; c++) acc[a][b2][c] = 0.f;

    int KT = K / 16;

#pragma unroll
    for (int s = 0; s < 2; s++) {
        int k0 = s * 16;
#pragma unroll
        for (int i = 0; i < 2; i++) {
            cpa16(sptr(&As[s * GSM_A + am[i] * SA + aj[i] * 4]),
                  A + (m0 + am[i]) * K + k0 + aj[i] * 4);
            cpa16(sptr(&Bs[s * GSM_B + bk[i] * SB + bj[i] * 4]),
                  B + (long)(k0 + bk[i]) * N + n0 + bj[i] * 4);
        }
        CP_COMMIT();
    }

    for (int kt = 0; kt < KT; kt++) {
        CP_WAIT(1);
        __syncthreads();

        if (kt + 2 < KT) {
            int s = (kt + 2) % 3;
            int k0 = (kt + 2) * 16;
#pragma unroll
            for (int i = 0; i < 2; i++) {
                cpa16(sptr(&As[s * GSM_A + am[i] * SA + aj[i] * 4]),
                      A + (m0 + am[i]) * K + k0 + aj[i] * 4);
                cpa16(sptr(&Bs[s * GSM_B + bk[i] * SB + bj[i] * 4]),
                      B + (long)(k0 + bk[i]) * N + n0 + bj[i] * 4);
            }
        }
        CP_COMMIT();

        const float* as = As + (kt % 3) * GSM_A;
        const float* bs = Bs + (kt % 3) * GSM_B;
#pragma unroll
        for (int ks = 0; ks < 2; ks++) {
            unsigned af[2][4];
#pragma unroll
            for (int mt = 0; mt < 2; mt++) {
                int r = wm + mt * 16 + gid, c = ks * 8 + tig;
                af[mt][0] = __float_as_uint(as[r * SA + c]);
                af[mt][1] = __float_as_uint(as[(r + 8) * SA + c]);
                af[mt][2] = __float_as_uint(as[r * SA + c + 4]);
                af[mt][3] = __float_as_uint(as[(r + 8) * SA + c + 4]);
            }
#pragma unroll
            for (int nt = 0; nt < 8; nt++) {
                unsigned bf[2];
                int c2 = wn + nt * 8 + gid;
                bf[0] = __float_as_uint(bs[(ks * 8 + tig) * SB + c2]);
                bf[1] = __float_as_uint(bs[(ks * 8 + tig + 4) * SB + c2]);
                mma8(acc[0][nt], af[0], bf);
                mma8(acc[1][nt], af[1], bf);
            }
        }
    }

    // epilogue
#pragma unroll
    for (int mt = 0; mt < 2; mt++) {
        long r0 = m0 + wm + mt * 16 + gid;
#pragma unroll
        for (int nt = 0; nt < 8; nt++) {
            int cc = n0 + wn + nt * 8 + 2 * tig;
            float b0 = bias[cc], b1 = bias[cc + 1];
#pragma unroll
            for (int half = 0; half < 2; half++) {
                long r = r0 + half * 8;
                float v0 = acc[mt][nt][half * 2 + 0] + b0;
                float v1 = acc[mt][nt][half * 2 + 1] + b1;
                if (EPI == 1) {
                    v0 += res[r * N + cc];
                    v1 += res[r * N + cc + 1];
                }
                if (EPI == 2) {
                    v0 = 0.5f * v0 * (1.f + erff(v0 * 0.70710678118654752f));
                    v1 = 0.5f * v1 * (1.f + erff(v1 * 0.70710678118654752f));
                }
                if (EPI == 0 || EPI == 2) { v0 = f2tf(v0); v1 = f2tf(v1); }
                *(float2*)(C + r * N + cc) = make_float2(v0, v1);
            }
        }
    }
}

// ---------------- tensor-core flash attention ---------------------------------
// qkv is already tf32-rounded (EPI 0) -> K/V/Q fragments need no cvt.
#define SK 68
#define SV 72
#define AT_PQ   (64 * SK)
#define AT_K    (64 * SK)
#define AT_V    (64 * SV)
#define ATT_SMEM ((AT_PQ + 2 * AT_K + 2 * AT_V) * 4)

__global__ void __launch_bounds__(128)
attn_tc(const float* __restrict__ qkv, float* __restrict__ ctx)
{
    extern __shared__ unsigned smu[];
    unsigned* PQ = smu;
    float* Ks = (float*)(smu + AT_PQ);
    float* Vs = (float*)(smu + AT_PQ + 2 * AT_K);

    int tid  = threadIdx.x;
    int lane = tid & 31, warp = tid >> 5;
    int gid = lane >> 2, tig = lane & 3;
    int qt = blockIdx.x, bh = blockIdx.y;
    int b = bh / HEADS, h = bh % HEADS;
    const float* base = qkv + (long)b * SEQ * QKV_LD + h * 64;
    int qn0 = qt * 64;

    int cm[8], cj[8];
#pragma unroll
    for (int i = 0; i < 8; i++) {
        int e = tid + i * 128;
        cm[i] = e >> 4; cj[i] = (e & 15) * 4;
    }

#pragma unroll
    for (int i = 0; i < 8; i++)
        cpa16(sptr(&PQ[cm[i] * SK + cj[i]]),
              base + (long)(qn0 + cm[i]) * QKV_LD + cj[i]);
    CP_COMMIT();
#pragma unroll
    for (int i = 0; i < 8; i++) {
        const float* rp = base + (long)cm[i] * QKV_LD;
        cpa16(sptr(&Ks[cm[i] * SK + cj[i]]), rp + EMBED + cj[i]);
        cpa16(sptr(&Vs[cm[i] * SV + cj[i]]), rp + 2 * EMBED + cj[i]);
    }
    CP_COMMIT();

    CP_WAIT(1);
    __syncthreads();

    // Q fragments: qkv already tf32; *0.125f (2^-3) stays tf32-exact
    unsigned qf[8][4];
    int qr = warp * 16 + gid;
#pragma unroll
    for (int ks = 0; ks < 8; ks++) {
        int c = ks * 8 + tig;
        qf[ks][0] = __float_as_uint(__uint_as_float(PQ[qr * SK + c]) * 0.125f);
        qf[ks][1] = __float_as_uint(__uint_as_float(PQ[(qr + 8) * SK + c]) * 0.125f);
        qf[ks][2] = __float_as_uint(__uint_as_float(PQ[qr * SK + c + 4]) * 0.125f);
        qf[ks][3] = __float_as_uint(__uint_as_float(PQ[(qr + 8) * SK + c + 4]) * 0.125f);
    }

    float o[8][4];
#pragma unroll
    for (int nt = 0; nt < 8; nt++)
#pragma unroll
        for (int j = 0; j < 4; j++) o[nt][j] = 0.f;
    float mA = -1e30f, mB = -1e30f, lA = 0.f, lB = 0.f;

    for (int kt = 0; kt < 16; kt++) {
        CP_WAIT(0);
        __syncthreads();

        if (kt + 1 < 16) {
            int bufn = (kt + 1) & 1;
            int kn0 = (kt + 1) * 64;
#pragma unroll
            for (int i = 0; i < 8; i++) {
                const float* rp = base + (long)(kn0 + cm[i]) * QKV_LD;
                cpa16(sptr(&Ks[bufn * AT_K + cm[i] * SK + cj[i]]), rp + EMBED + cj[i]);
                cpa16(sptr(&Vs[bufn * AT_V + cm[i] * SV + cj[i]]), rp + 2 * EMBED + cj[i]);
            }
        }
        CP_COMMIT();

        const float* kb = Ks + (kt & 1) * AT_K;
        const float* vb = Vs + (kt & 1) * AT_V;

        float s[8][4];
#pragma unroll
        for (int nt = 0; nt < 8; nt++)
#pragma unroll
            for (int j = 0; j < 4; j++) s[nt][j] = 0.f;
#pragma unroll
        for (int ks = 0; ks < 8; ks++) {
            int c = ks * 8 + tig;
#pragma unroll
            for (int nt = 0; nt < 8; nt++) {
                unsigned bf[2];
                int n = nt * 8 + gid;
                bf[0] = __float_as_uint(kb[n * SK + c]);
                bf[1] = __float_as_uint(kb[n * SK + c + 4]);
                mma8(s[nt], qf[ks], bf);
            }
        }

        float mlA = -1e30f, mlB = -1e30f;
#pragma unroll
        for (int nt = 0; nt < 8; nt++) {
            mlA = fmaxf(mlA, fmaxf(s[nt][0], s[nt][1]));
            mlB = fmaxf(mlB, fmaxf(s[nt][2], s[nt][3]));
        }
#pragma unroll
        for (int off = 1; off < 4; off <<= 1) {
            mlA = fmaxf(mlA, __shfl_xor_sync(0xffffffffu, mlA, off));
            mlB = fmaxf(mlB, __shfl_xor_sync(0xffffffffu, mlB, off));
        }
        float mnA = fmaxf(mA, mlA), mnB = fmaxf(mB, mlB);
        float aA = __expf(mA - mnA), aB = __expf(mB - mnB);
        float lsA = 0.f, lsB = 0.f;
#pragma unroll
        for (int nt = 0; nt < 8; nt++) {
            s[nt][0] = __expf(s[nt][0] - mnA); lsA += s[nt][0];
            s[nt][1] = __expf(s[nt][1] - mnA); lsA += s[nt][1];
            s[nt][2] = __expf(s[nt][2] - mnB); lsB += s[nt][2];
            s[nt][3] = __expf(s[nt][3] - mnB); lsB += s[nt][3];
        }
#pragma unroll
        for (int off = 1; off < 4; off <<= 1) {
            lsA += __shfl_xor_sync(0xffffffffu, lsA, off);
            lsB += __shfl_xor_sync(0xffffffffu, lsB, off);
        }
        lA = lA * aA + lsA; mA = mnA;
        lB = lB * aB + lsB; mB = mnB;
#pragma unroll
        for (int nt = 0; nt < 8; nt++) {
            o[nt][0] *= aA; o[nt][1] *= aA;
            o[nt][2] *= aB; o[nt][3] *= aB;
        }

        // P -> warp-private smem rows
#pragma unroll
        for (int nt = 0; nt < 8; nt++) {
            int col = nt * 8 + 2 * tig;
            *(uint2*)&PQ[qr * SK + col] =
                make_uint2(f2t(s[nt][0]), f2t(s[nt][1]));
            *(uint2*)&PQ[(qr + 8) * SK + col] =
                make_uint2(f2t(s[nt][2]), f2t(s[nt][3]));
        }
        __syncwarp();

#pragma unroll
        for (int ks = 0; ks < 8; ks++) {
            unsigned pf[4];
            int c = ks * 8 + tig;
            pf[0] = PQ[qr * SK + c];
            pf[1] = PQ[(qr + 8) * SK + c];
            pf[2] = PQ[qr * SK + c + 4];
            pf[3] = PQ[(qr + 8) * SK + c + 4];
#pragma unroll
            for (int nt = 0; nt < 8; nt++) {
                unsigned bf[2];
                int n = nt * 8 + gid;
                bf[0] = __float_as_uint(vb[(ks * 8 + tig) * SV + n]);
                bf[1] = __float_as_uint(vb[(ks * 8 + tig + 4) * SV + n]);
                mma8(o[nt], pf, bf);
            }
        }
        __syncwarp();
    }

    // normalize + write ctx (rounded: feeds proj GEMM as A operand)
    float rA = 1.f / lA, rB = 1.f / lB;
    long row0 = (long)(b * SEQ + qn0 + qr);
#pragma unroll
    for (int nt = 0; nt < 8; nt++) {
        int col = h * 64 + nt * 8 + 2 * tig;
        *(float2*)(ctx + row0 * EMBED + col) =
            make_float2(f2tf(o[nt][0] * rA), f2tf(o[nt][1] * rA));
        *(float2*)(ctx + (row0 + 8) * EMBED + col) =
            make_float2(f2tf(o[nt][2] * rB), f2tf(o[nt][3] * rB));
    }
}

// ---------------- launcher ----------------------------------------------------
extern "C" void kernel_launch(void* const* d_in, const int* in_sizes, int n_in,
                              void* d_out, int out_size)
{
    (void)in_sizes; (void)n_in; (void)out_size;
    const float* x      = (const float*)d_in[0];
    const float* n1g    = (const float*)d_in[1];
    const float* n1b    = (const float*)d_in[2];
    const float* qkv_w  = (const float*)d_in[3];
    const float* qkv_b  = (const float*)d_in[4];
    const float* proj_w = (const float*)d_in[5];
    const float* proj_b = (const float*)d_in[6];
    const float* n2g    = (const float*)d_in[7];
    const float* n2b    = (const float*)d_in[8];
    const float* fc1_w  = (const float*)d_in[9];
    const float* fc1_b  = (const float*)d_in[10];
    const float* fc2_w  = (const float*)d_in[11];
    const float* fc2_b  = (const float*)d_in[12];
    float* out = (float*)d_out;

    float *h, *qkv, *ctx, *x1, *h2, *w;
    cudaGetSymbolAddress((void**)&h,   g_h);
    cudaGetSymbolAddress((void**)&qkv, g_qkv);
    cudaGetSymbolAddress((void**)&ctx, g_ctx);
    cudaGetSymbolAddress((void**)&x1,  g_x1);
    cudaGetSymbolAddress((void**)&h2,  g_h2);
    cudaGetSymbolAddress((void**)&w,   g_w);

    const float* wq = w;
    const float* wp = w + WSZ_QKV;
    const float* w1 = w + WSZ_QKV + WSZ_PROJ;
    const float* w2 = w + WSZ_QKV + WSZ_PROJ + WSZ_FC1;

    cudaFuncSetAttribute(gemm_tc<0>, cudaFuncAttributeMaxDynamicSharedMemorySize, GEMM_SMEM);
    cudaFuncSetAttribute(gemm_tc<1>, cudaFuncAttributeMaxDynamicSharedMemorySize, GEMM_SMEM);
    cudaFuncSetAttribute(gemm_tc<2>, cudaFuncAttributeMaxDynamicSharedMemorySize, GEMM_SMEM);
    cudaFuncSetAttribute(attn_tc,    cudaFuncAttributeMaxDynamicSharedMemorySize, ATT_SMEM);

    cvt_weights<<<WSZ_TOT / 4 / 256, 256>>>(qkv_w, proj_w, fc1_w, fc2_w, (float*)w);
    ln_kernel<<<NTOK, 128>>>(x, n1g, n1b, h);
    gemm_tc<0><<<dim3(3 * EMBED / 128, NTOK / 128), 256, GEMM_SMEM>>>(
        h, wq, qkv_b, nullptr, qkv, NTOK, 3 * EMBED, EMBED);
    attn_tc<<<dim3(SEQ / 64, BATCH * HEADS), 128, ATT_SMEM>>>(qkv, ctx);
    gemm_tc<1><<<dim3(EMBED / 128, NTOK / 128), 256, GEMM_SMEM>>>(
        ctx, wp, proj_b, x, x1, NTOK, EMBED, EMBED);
    ln_kernel<<<NTOK, 128>>>(x1, n2g, n2b, h);
    gemm_tc<2><<<dim3(MLP_HID / 128, NTOK / 128), 256, GEMM_SMEM>>>(
        h, w1, fc1_b, nullptr, h2, NTOK, MLP_HID, EMBED);
    gemm_tc<1><<<dim3(EMBED / 128, NTOK / 128), 256, GEMM_SMEM>>>(
        h2, w2, fc2_b, x1, out, NTOK, EMBED, MLP_HID);
}